// round 3
// baseline (speedup 1.0000x reference)
#include <cuda_runtime.h>
#include <cuda_bf16.h>
#include <cstdint>

// Problem constants
#define BB 32
#define LL 32768
#define HH 32
#define NN2 8
#define CLEN 128
#define NCHUNK 256   // LL / CLEN

typedef unsigned long long ull;

// ---------- f32x2 packed helpers (sm_100+) ----------
__device__ __forceinline__ ull fma2(ull a, ull b, ull c) {
    ull d; asm("fma.rn.f32x2 %0,%1,%2,%3;" : "=l"(d) : "l"(a), "l"(b), "l"(c)); return d;
}
__device__ __forceinline__ ull mul2(ull a, ull b) {
    ull d; asm("mul.rn.f32x2 %0,%1,%2;" : "=l"(d) : "l"(a), "l"(b)); return d;
}
__device__ __forceinline__ ull add2(ull a, ull b) {
    ull d; asm("add.rn.f32x2 %0,%1,%2;" : "=l"(d) : "l"(a), "l"(b)); return d;
}
__device__ __forceinline__ ull pack2(float lo, float hi) {
    ull d; asm("mov.b64 %0,{%1,%2};" : "=l"(d) : "f"(lo), "f"(hi)); return d;
}
__device__ __forceinline__ void unpack2(ull a, float& lo, float& hi) {
    asm("mov.b64 {%0,%1},%2;" : "=f"(lo), "=f"(hi) : "l"(a));
}
__device__ __forceinline__ ull neg2(ull a) {  // flip sign of both packed floats (LOP3, alu pipe)
    return a ^ 0x8000000080000000ULL;
}

// ---------- device scratch ----------
__device__ ull g_Bc [(size_t)BB * NCHUNK * 8 * HH];   // per-chunk local aggregates
__device__ ull g_Sin[(size_t)BB * NCHUNK * 8 * HH];   // per-chunk incoming states
__device__ float g_wre[HH * NN2],   g_wim[HH * NN2];     // w
__device__ float g_w2re[HH * NN2],  g_w2im[HH * NN2];    // w^2
__device__ float g_ct2re[HH * NN2], g_ct2im[HH * NN2];   // 2*Ct folded
__device__ float g_wclre[HH * NN2], g_wclim[HH * NN2];   // w^CLEN
__device__ float g_w8re[HH * NN2],  g_w8im[HH * NN2];    // w^(8*CLEN)
__device__ float g_gamma[BB * HH], g_beta[BB * HH];

// ---------- precompute ----------
__global__ void precompute_kernel(const float* __restrict__ log_dt,
                                  const float* __restrict__ C_re,
                                  const float* __restrict__ C_im,
                                  const float* __restrict__ log_A_real,
                                  const float* __restrict__ A_imag,
                                  const float* __restrict__ cond,
                                  const float* __restrict__ film_W,
                                  const float* __restrict__ film_b) {
    int tid = threadIdx.x;
    if (tid < HH * NN2) {
        int h = tid >> 3;
        double dt  = exp((double)log_dt[h]);
        double Are = -exp((double)log_A_real[tid]);
        double Aim = (double)A_imag[tid];
        double dre = Are * dt, dim = Aim * dt;
        double er  = exp(dre);
        double wre = er * cos(dim), wim = er * sin(dim);
        double nre = wre - 1.0, nim = wim;
        double a2  = Are * Are + Aim * Aim;
        double qre = (nre * Are + nim * Aim) / a2;
        double qim = (nim * Are - nre * Aim) / a2;
        double cr = (double)C_re[tid], ci = (double)C_im[tid];
        g_wre[tid] = (float)wre;
        g_wim[tid] = (float)wim;
        g_ct2re[tid] = (float)(2.0 * (cr * qre - ci * qim));
        g_ct2im[tid] = (float)(2.0 * (cr * qim + ci * qre));
        // w^2 from fp32-rounded w
        double pr = (double)(float)wre, pi = (double)(float)wim;
        double r2 = pr * pr - pi * pi; pi = 2.0 * pr * pi; pr = r2;
        g_w2re[tid] = (float)pr;
        g_w2im[tid] = (float)pi;
        // w^CLEN from fp32 w2 (CLEN=128 -> 6 squarings)
        pr = (double)(float)pr; pi = (double)(float)pi;
        for (int i = 0; i < 6; i++) {
            r2 = pr * pr - pi * pi; pi = 2.0 * pr * pi; pr = r2;
        }
        g_wclre[tid] = (float)pr;
        g_wclim[tid] = (float)pi;
        // w^(8*CLEN) from fp32 wcl (3 squarings)
        pr = (double)(float)pr; pi = (double)(float)pi;
        for (int i = 0; i < 3; i++) {
            r2 = pr * pr - pi * pi; pi = 2.0 * pr * pi; pr = r2;
        }
        g_w8re[tid] = (float)pr;
        g_w8im[tid] = (float)pi;
    }
    if (tid < BB * HH) {
        int b = tid >> 5, h = tid & 31;
        float g = film_b[h], be = film_b[HH + h];
        #pragma unroll
        for (int c = 0; c < 4; c++) {
            float cv = cond[b * 4 + c];
            g  = fmaf(cv, film_W[c * (2 * HH) + h], g);
            be = fmaf(cv, film_W[c * (2 * HH) + HH + h], be);
        }
        g_gamma[tid] = g;
        g_beta[tid]  = be;
    }
}

// ---------- pass A: per-chunk local aggregates (2-step recurrence, 64-reg budget) ----------
__global__ __launch_bounds__(128, 8) void passA_kernel(const float* __restrict__ x) {
    int gw = (blockIdx.x * 128 + threadIdx.x) >> 5;  // global warp = (b, c)
    int h  = threadIdx.x & 31;
    int b  = gw >> 8;              // / NCHUNK
    int c  = gw & (NCHUNK - 1);
    int hb = h * NN2;

    ull wre[4], wim[4], w2re[4], w2im[4];
    #pragma unroll
    for (int v = 0; v < 4; v++) {
        wre[v]  = pack2(g_wre [hb + 2 * v], g_wre [hb + 2 * v + 1]);
        wim[v]  = pack2(g_wim [hb + 2 * v], g_wim [hb + 2 * v + 1]);
        w2re[v] = pack2(g_w2re[hb + 2 * v], g_w2re[hb + 2 * v + 1]);
        w2im[v] = pack2(g_w2im[hb + 2 * v], g_w2im[hb + 2 * v + 1]);
    }
    ull sre[4], sim[4];
    #pragma unroll
    for (int v = 0; v < 4; v++) { sre[v] = 0ull; sim[v] = 0ull; }

    const float* xp = x + ((b * LL) + c * CLEN) * HH + h;
    #pragma unroll 2
    for (int j = 0; j < CLEN / 2; j++) {
        float u0 = xp[(2 * j) * HH];
        float u1 = xp[(2 * j + 1) * HH];
        ull u0_2 = pack2(u0, u0);
        ull u1_2 = pack2(u1, u1);
        #pragma unroll
        for (int v = 0; v < 4; v++) {
            // q = w*u0 + u1
            ull qre = fma2(wre[v], u0_2, u1_2);
            ull qim = mul2(wim[v], u0_2);
            // s = w2 * s + q
            ull t  = fma2(neg2(w2im[v]), sim[v], qre);
            ull ni = fma2(w2im[v], sre[v], fma2(w2re[v], sim[v], qim));
            sre[v] = fma2(w2re[v], sre[v], t);
            sim[v] = ni;
        }
    }
    ull* o = g_Bc + (size_t)(b * NCHUNK + c) * 8 * HH + h;
    #pragma unroll
    for (int v = 0; v < 4; v++) { o[v * HH] = sre[v]; o[(4 + v) * HH] = sim[v]; }
}

// ---------- pass B: parallel chunk-level scan, one warp per (b,h) ----------
__global__ __launch_bounds__(128) void passB_kernel() {
    int gw   = (blockIdx.x * 128 + threadIdx.x) >> 5;  // (b,h), 1024 warps
    int lane = threadIdx.x & 31;
    int b = gw >> 5, h = gw & 31;
    int hb = h * NN2;

    ull clre[4], clim[4], Pre[4], Pim[4];
    #pragma unroll
    for (int v = 0; v < 4; v++) {
        clre[v] = pack2(g_wclre[hb + 2 * v], g_wclre[hb + 2 * v + 1]);
        clim[v] = pack2(g_wclim[hb + 2 * v], g_wclim[hb + 2 * v + 1]);
        Pre[v]  = pack2(g_w8re [hb + 2 * v], g_w8re [hb + 2 * v + 1]);
        Pim[v]  = pack2(g_w8im [hb + 2 * v], g_w8im [hb + 2 * v + 1]);
    }

    // lane owns 8 consecutive chunks: serial local compose S = wcl*S + Bc
    ull Sre[4], Sim[4];
    #pragma unroll
    for (int v = 0; v < 4; v++) { Sre[v] = 0ull; Sim[v] = 0ull; }
    ull* bc = g_Bc + (size_t)(b * NCHUNK + lane * 8) * 8 * HH + h;
    #pragma unroll
    for (int k = 0; k < 8; k++) {
        int base = k * 8 * HH;
        #pragma unroll
        for (int v = 0; v < 4; v++) {
            ull bre = bc[base + v * HH];
            ull bim = bc[base + (4 + v) * HH];
            ull t  = fma2(neg2(clim[v]), Sim[v], bre);
            ull ni = fma2(clim[v], Sre[v], fma2(clre[v], Sim[v], bim));
            Sre[v] = fma2(clre[v], Sre[v], t);
            Sim[v] = ni;
        }
    }

    // Kogge-Stone inclusive scan over lanes (affine compose)
    #pragma unroll
    for (int d = 1; d < 32; d <<= 1) {
        #pragma unroll
        for (int v = 0; v < 4; v++) {
            ull Spre = __shfl_up_sync(0xffffffffu, Sre[v], d);
            ull Spim = __shfl_up_sync(0xffffffffu, Sim[v], d);
            ull Ppre = __shfl_up_sync(0xffffffffu, Pre[v], d);
            ull Ppim = __shfl_up_sync(0xffffffffu, Pim[v], d);
            ull nSre = fma2(Pre[v], Spre, fma2(neg2(Pim[v]), Spim, Sre[v]));
            ull nSim = fma2(Pim[v], Spre, fma2(Pre[v], Spim, Sim[v]));
            ull nPre = fma2(Ppre, Pre[v], mul2(neg2(Ppim), Pim[v]));
            ull nPim = fma2(Ppim, Pre[v], mul2(Ppre, Pim[v]));
            if (lane >= d) {
                Sre[v] = nSre; Sim[v] = nSim;
                Pre[v] = nPre; Pim[v] = nPim;
            }
        }
    }

    // exclusive prefix
    ull Ere[4], Eim[4];
    #pragma unroll
    for (int v = 0; v < 4; v++) {
        Ere[v] = __shfl_up_sync(0xffffffffu, Sre[v], 1);
        Eim[v] = __shfl_up_sync(0xffffffffu, Sim[v], 1);
        if (lane == 0) { Ere[v] = 0ull; Eim[v] = 0ull; }
    }

    // re-walk local 8 chunks: write incoming state, then advance
    ull* si = g_Sin + (size_t)(b * NCHUNK + lane * 8) * 8 * HH + h;
    #pragma unroll
    for (int k = 0; k < 8; k++) {
        int base = k * 8 * HH;
        #pragma unroll
        for (int v = 0; v < 4; v++) {
            si[base + v * HH]       = Ere[v];
            si[base + (4 + v) * HH] = Eim[v];
        }
        #pragma unroll
        for (int v = 0; v < 4; v++) {
            ull bre = bc[base + v * HH];
            ull bim = bc[base + (4 + v) * HH];
            ull t  = fma2(neg2(clim[v]), Eim[v], bre);
            ull ni = fma2(clim[v], Ere[v], fma2(clre[v], Eim[v], bim));
            Ere[v] = fma2(clre[v], Ere[v], t);
            Eim[v] = ni;
        }
    }
}

// ---------- pass C: replay + skip + FiLM + gelu (negated-imag state, 64-reg budget) ----------
__global__ __launch_bounds__(128, 8) void passC_kernel(const float* __restrict__ x,
                                                       const float* __restrict__ D,
                                                       float* __restrict__ out) {
    int gw = (blockIdx.x * 128 + threadIdx.x) >> 5;
    int h  = threadIdx.x & 31;
    int b  = gw >> 8;
    int c  = gw & (NCHUNK - 1);
    int hb = h * NN2;

    ull wre[4], wim[4], cre[4], cim[4];
    #pragma unroll
    for (int v = 0; v < 4; v++) {
        wre[v] = pack2(g_wre[hb + 2 * v], g_wre[hb + 2 * v + 1]);
        wim[v] = pack2(g_wim[hb + 2 * v], g_wim[hb + 2 * v + 1]);
        cre[v] = pack2(g_ct2re[hb + 2 * v], g_ct2re[hb + 2 * v + 1]);
        cim[v] = pack2(g_ct2im[hb + 2 * v], g_ct2im[hb + 2 * v + 1]);
    }
    float Dh  = D[h];
    float gam = g_gamma[b * HH + h];
    float bet = g_beta[b * HH + h];

    // state: sre, simn = -sim  (so recurrence re-part and dot need no extra negs)
    ull sre[4], simn[4];
    const ull* si = g_Sin + (size_t)(b * NCHUNK + c) * 8 * HH + h;
    #pragma unroll
    for (int v = 0; v < 4; v++) { sre[v] = si[v * HH]; simn[v] = neg2(si[(4 + v) * HH]); }

    const float* xp = x   + ((b * LL) + c * CLEN) * HH + h;
    float*       op = out + ((b * LL) + c * CLEN) * HH + h;

    #pragma unroll 4
    for (int j = 0; j < CLEN; j++) {
        float u = xp[j * HH];
        ull u2 = pack2(u, u);
        #pragma unroll
        for (int v = 0; v < 4; v++) {
            // sre'  = wre*sre - wim*sim + u  = wre*sre + wim*simn + u
            // simn' = -(wim*sre + wre*sim)   = -wim*sre + wre*simn
            ull t  = fma2(wim[v], simn[v], u2);
            ull ni = fma2(neg2(wim[v]), sre[v], mul2(wre[v], simn[v]));
            sre[v]  = fma2(wre[v], sre[v], t);
            simn[v] = ni;
        }
        // y = sum(cre*sre) - sum(cim*sim) + D*u = sum(cre*sre) + sum(cim*simn) + D*u
        ull accA = pack2(Dh * u, 0.0f);
        ull accB = mul2(cim[0], simn[0]);
        accA = fma2(cre[0], sre[0], accA);
        accB = fma2(cim[1], simn[1], accB);
        accA = fma2(cre[1], sre[1], accA);
        accB = fma2(cim[2], simn[2], accB);
        accA = fma2(cre[2], sre[2], accA);
        accB = fma2(cim[3], simn[3], accB);
        accA = fma2(cre[3], sre[3], accA);
        ull acc = add2(accA, accB);
        float alo, ahi; unpack2(acc, alo, ahi);
        float y = alo + ahi;
        // FiLM + gelu(tanh)
        float z = fmaf(gam, y, bet);
        float t2 = z * z;
        float p  = fmaf(0.0356774081f, t2, 0.7978845608f);
        float inner = z * p;
        float th; asm("tanh.approx.f32 %0, %1;" : "=f"(th) : "f"(inner));
        float hz = 0.5f * z;
        op[j * HH] = fmaf(hz, th, hz);
    }
}

extern "C" void kernel_launch(void* const* d_in, const int* in_sizes, int n_in,
                              void* d_out, int out_size) {
    const float* x          = (const float*)d_in[0];
    const float* cond       = (const float*)d_in[1];
    const float* log_dt     = (const float*)d_in[2];
    const float* C_re       = (const float*)d_in[3];
    const float* C_im       = (const float*)d_in[4];
    const float* log_A_real = (const float*)d_in[5];
    const float* A_imag     = (const float*)d_in[6];
    const float* D          = (const float*)d_in[7];
    const float* film_W     = (const float*)d_in[8];
    const float* film_b     = (const float*)d_in[9];
    float* out = (float*)d_out;

    precompute_kernel<<<1, 1024>>>(log_dt, C_re, C_im, log_A_real, A_imag, cond, film_W, film_b);
    passA_kernel<<<(BB * NCHUNK) / 4, 128>>>(x);
    passB_kernel<<<(BB * HH) / 4, 128>>>();
    passC_kernel<<<(BB * NCHUNK) / 4, 128>>>(x, D, out);
}

// round 5
// speedup vs baseline: 1.2931x; 1.2931x over previous
#include <cuda_runtime.h>
#include <cuda_bf16.h>
#include <cstdint>

// Problem constants
#define BB 32
#define LL 32768
#define HH 32
#define NN2 8
#define CLEN 128
#define NCHUNK 256   // LL / CLEN

typedef unsigned long long ull;

// ---------- f32x2 packed helpers (sm_100+) ----------
__device__ __forceinline__ ull fma2(ull a, ull b, ull c) {
    ull d; asm("fma.rn.f32x2 %0,%1,%2,%3;" : "=l"(d) : "l"(a), "l"(b), "l"(c)); return d;
}
__device__ __forceinline__ ull mul2(ull a, ull b) {
    ull d; asm("mul.rn.f32x2 %0,%1,%2;" : "=l"(d) : "l"(a), "l"(b)); return d;
}
__device__ __forceinline__ ull add2(ull a, ull b) {
    ull d; asm("add.rn.f32x2 %0,%1,%2;" : "=l"(d) : "l"(a), "l"(b)); return d;
}
__device__ __forceinline__ ull pack2(float lo, float hi) {
    ull d; asm("mov.b64 %0,{%1,%2};" : "=l"(d) : "f"(lo), "f"(hi)); return d;
}
__device__ __forceinline__ void unpack2(ull a, float& lo, float& hi) {
    asm("mov.b64 {%0,%1},%2;" : "=f"(lo), "=f"(hi) : "l"(a));
}
__device__ __forceinline__ ull neg2(ull a) {
    return a ^ 0x8000000080000000ULL;
}

// ---------- device scratch ----------
__device__ ull g_Bc [(size_t)BB * NCHUNK * 8 * HH];   // per-chunk complex aggregates
__device__ ull g_Sin[(size_t)BB * NCHUNK * 8 * HH];   // per-chunk incoming complex states
// Biquad coefficients (per mode)
__device__ float g_a1[HH * NN2], g_a2[HH * NN2];           // poles
__device__ float g_b0[HH * NN2], g_b1[HH * NN2];           // output taps
__device__ float g_k1[HH * NN2], g_k2[HH * NN2];           // complex s -> (v1,v2)
__device__ float g_m1[HH * NN2], g_m2[HH * NN2];           // (v1,v2) -> complex s
// Complex chunk-composition constants (passB)
__device__ float g_wclre[HH * NN2], g_wclim[HH * NN2];     // w^CLEN
__device__ float g_w8re[HH * NN2],  g_w8im[HH * NN2];      // w^(8*CLEN)
__device__ float g_gamma[BB * HH], g_beta[BB * HH];

// ---------- precompute ----------
__global__ void precompute_kernel(const float* __restrict__ log_dt,
                                  const float* __restrict__ C_re,
                                  const float* __restrict__ C_im,
                                  const float* __restrict__ log_A_real,
                                  const float* __restrict__ A_imag,
                                  const float* __restrict__ cond,
                                  const float* __restrict__ film_W,
                                  const float* __restrict__ film_b) {
    int tid = threadIdx.x;
    if (tid < HH * NN2) {
        int h = tid >> 3;
        bool mode0 = (tid & 7) == 0;   // A_imag == 0 -> real first-order mode
        double dt  = exp((double)log_dt[h]);
        double Are = -exp((double)log_A_real[tid]);
        double Aim = (double)A_imag[tid];
        double dre = Are * dt, dim = Aim * dt;
        double er  = exp(dre);
        double wre = er * cos(dim), wim = er * sin(dim);
        double nre = wre - 1.0, nim = wim;
        double a2d = Are * Are + Aim * Aim;
        double qre = (nre * Are + nim * Aim) / a2d;
        double qim = (nim * Are - nre * Aim) / a2d;
        double cr = (double)C_re[tid], ci = (double)C_im[tid];
        double ct2re = 2.0 * (cr * qre - ci * qim);   // 2*Re(Ct)
        double ct2im = 2.0 * (cr * qim + ci * qre);   // 2*Im(Ct)
        // Biquad: v[t] = u + a1 v1 + a2 v2 ; y = b0 v + b1 v1
        if (mode0) {
            g_a1[tid] = (float)wre;
            g_a2[tid] = 0.0f;
            g_b0[tid] = (float)ct2re;
            g_b1[tid] = 0.0f;
            g_k1[tid] = 0.0f;  g_k2[tid] = 0.0f;   // sim==0 for this mode
            g_m1[tid] = 0.0f;  g_m2[tid] = 0.0f;
        } else {
            g_a1[tid] = (float)(2.0 * wre);
            g_a2[tid] = (float)(-(wre * wre + wim * wim));
            g_b0[tid] = (float)ct2re;
            g_b1[tid] = (float)(-(ct2re * wre + ct2im * wim));
            g_k1[tid] = (float)(wre / wim);
            g_k2[tid] = (float)(1.0 / wim);
            g_m1[tid] = (float)(-wre);
            g_m2[tid] = (float)wim;
        }
        // w^CLEN from fp32-rounded w (CLEN=128 -> 7 squarings)
        double pr = (double)(float)wre, pi = (double)(float)wim;
        for (int i = 0; i < 7; i++) {
            double r2 = pr * pr - pi * pi; pi = 2.0 * pr * pi; pr = r2;
        }
        g_wclre[tid] = (float)pr;
        g_wclim[tid] = (float)pi;
        // w^(8*CLEN) (3 more squarings from fp32 wcl)
        pr = (double)(float)pr; pi = (double)(float)pi;
        for (int i = 0; i < 3; i++) {
            double r2 = pr * pr - pi * pi; pi = 2.0 * pr * pi; pr = r2;
        }
        g_w8re[tid] = (float)pr;
        g_w8im[tid] = (float)pi;
    }
    if (tid < BB * HH) {
        int b = tid >> 5, h = tid & 31;
        float g = film_b[h], be = film_b[HH + h];
        #pragma unroll
        for (int c = 0; c < 4; c++) {
            float cv = cond[b * 4 + c];
            g  = fmaf(cv, film_W[c * (2 * HH) + h], g);
            be = fmaf(cv, film_W[c * (2 * HH) + HH + h], be);
        }
        g_gamma[tid] = g;
        g_beta[tid]  = be;
    }
}

// ---------- pass A: per-chunk aggregates via biquad all-pole state ----------
__global__ __launch_bounds__(128, 7) void passA_kernel(const float* __restrict__ x) {
    int gw = (blockIdx.x * 128 + threadIdx.x) >> 5;
    int h  = threadIdx.x & 31;
    int b  = gw >> 8;
    int c  = gw & (NCHUNK - 1);
    int hb = h * NN2;

    ull a1[4], a2[4];
    #pragma unroll
    for (int v = 0; v < 4; v++) {
        a1[v] = pack2(g_a1[hb + 2 * v], g_a1[hb + 2 * v + 1]);
        a2[v] = pack2(g_a2[hb + 2 * v], g_a2[hb + 2 * v + 1]);
    }
    ull v1[4], v2[4];
    #pragma unroll
    for (int v = 0; v < 4; v++) { v1[v] = 0ull; v2[v] = 0ull; }

    const float* xp = x + ((b * LL) + c * CLEN) * HH + h;
    #pragma unroll 4
    for (int j = 0; j < CLEN / 2; j++) {
        float u0 = xp[(2 * j) * HH];
        float u1 = xp[(2 * j + 1) * HH];
        ull u02 = pack2(u0, u0);
        ull u12 = pack2(u1, u1);
        #pragma unroll
        for (int v = 0; v < 4; v++) {
            // step even: new v into v2 slot
            ull t0 = fma2(a2[v], v2[v], u02);
            v2[v]  = fma2(a1[v], v1[v], t0);
            // step odd: new v into v1 slot
            ull t1 = fma2(a2[v], v1[v], u12);
            v1[v]  = fma2(a1[v], v2[v], t1);
        }
    }
    // after loop: v1 = v[last], v2 = v[last-1]; convert to complex s and store
    ull* o = g_Bc + (size_t)(b * NCHUNK + c) * 8 * HH + h;
    #pragma unroll
    for (int v = 0; v < 4; v++) {
        ull m1 = pack2(g_m1[hb + 2 * v], g_m1[hb + 2 * v + 1]);
        ull m2 = pack2(g_m2[hb + 2 * v], g_m2[hb + 2 * v + 1]);
        o[v * HH]       = fma2(m1, v2[v], v1[v]);   // sre = v + m1*vprev (mode0: sre = v)
        o[(4 + v) * HH] = mul2(m2, v2[v]);          // sim = m2*vprev   (mode0: 0)
    }
}

// ---------- pass B: parallel chunk-level scan (complex), one warp per (b,h) ----------
__global__ __launch_bounds__(128) void passB_kernel() {
    int gw   = (blockIdx.x * 128 + threadIdx.x) >> 5;  // (b,h), 1024 warps
    int lane = threadIdx.x & 31;
    int b = gw >> 5, h = gw & 31;
    int hb = h * NN2;

    ull clre[4], clim[4], Pre[4], Pim[4];
    #pragma unroll
    for (int v = 0; v < 4; v++) {
        clre[v] = pack2(g_wclre[hb + 2 * v], g_wclre[hb + 2 * v + 1]);
        clim[v] = pack2(g_wclim[hb + 2 * v], g_wclim[hb + 2 * v + 1]);
        Pre[v]  = pack2(g_w8re [hb + 2 * v], g_w8re [hb + 2 * v + 1]);
        Pim[v]  = pack2(g_w8im [hb + 2 * v], g_w8im [hb + 2 * v + 1]);
    }

    // lane owns 8 consecutive chunks: serial local compose S = wcl*S + Bc
    ull Sre[4], Sim[4];
    #pragma unroll
    for (int v = 0; v < 4; v++) { Sre[v] = 0ull; Sim[v] = 0ull; }
    ull* bc = g_Bc + (size_t)(b * NCHUNK + lane * 8) * 8 * HH + h;
    #pragma unroll
    for (int k = 0; k < 8; k++) {
        int base = k * 8 * HH;
        #pragma unroll
        for (int v = 0; v < 4; v++) {
            ull bre = bc[base + v * HH];
            ull bim = bc[base + (4 + v) * HH];
            ull t  = fma2(neg2(clim[v]), Sim[v], bre);
            ull ni = fma2(clim[v], Sre[v], fma2(clre[v], Sim[v], bim));
            Sre[v] = fma2(clre[v], Sre[v], t);
            Sim[v] = ni;
        }
    }

    // Kogge-Stone inclusive scan over lanes (affine compose)
    #pragma unroll
    for (int d = 1; d < 32; d <<= 1) {
        #pragma unroll
        for (int v = 0; v < 4; v++) {
            ull Spre = __shfl_up_sync(0xffffffffu, Sre[v], d);
            ull Spim = __shfl_up_sync(0xffffffffu, Sim[v], d);
            ull Ppre = __shfl_up_sync(0xffffffffu, Pre[v], d);
            ull Ppim = __shfl_up_sync(0xffffffffu, Pim[v], d);
            ull nSre = fma2(Pre[v], Spre, fma2(neg2(Pim[v]), Spim, Sre[v]));
            ull nSim = fma2(Pim[v], Spre, fma2(Pre[v], Spim, Sim[v]));
            ull nPre = fma2(Ppre, Pre[v], mul2(neg2(Ppim), Pim[v]));
            ull nPim = fma2(Ppim, Pre[v], mul2(Ppre, Pim[v]));
            if (lane >= d) {
                Sre[v] = nSre; Sim[v] = nSim;
                Pre[v] = nPre; Pim[v] = nPim;
            }
        }
    }

    // exclusive prefix
    ull Ere[4], Eim[4];
    #pragma unroll
    for (int v = 0; v < 4; v++) {
        Ere[v] = __shfl_up_sync(0xffffffffu, Sre[v], 1);
        Eim[v] = __shfl_up_sync(0xffffffffu, Sim[v], 1);
        if (lane == 0) { Ere[v] = 0ull; Eim[v] = 0ull; }
    }

    // re-walk local 8 chunks: write incoming state, then advance
    ull* si = g_Sin + (size_t)(b * NCHUNK + lane * 8) * 8 * HH + h;
    #pragma unroll
    for (int k = 0; k < 8; k++) {
        int base = k * 8 * HH;
        #pragma unroll
        for (int v = 0; v < 4; v++) {
            si[base + v * HH]       = Ere[v];
            si[base + (4 + v) * HH] = Eim[v];
        }
        #pragma unroll
        for (int v = 0; v < 4; v++) {
            ull bre = bc[base + v * HH];
            ull bim = bc[base + (4 + v) * HH];
            ull t  = fma2(neg2(clim[v]), Eim[v], bre);
            ull ni = fma2(clim[v], Ere[v], fma2(clre[v], Eim[v], bim));
            Ere[v] = fma2(clre[v], Ere[v], t);
            Eim[v] = ni;
        }
    }
}

// epilogue: FiLM + gelu(tanh)
__device__ __forceinline__ float film_gelu(float y, float gam, float bet) {
    float z = fmaf(gam, y, bet);
    float t2 = z * z;
    float p  = fmaf(0.0356774081f, t2, 0.7978845608f);
    float inner = z * p;
    float th; asm("tanh.approx.f32 %0, %1;" : "=f"(th) : "f"(inner));
    float hz = 0.5f * z;
    return fmaf(hz, th, hz);
}

// ---------- pass C: biquad replay + skip + FiLM + gelu ----------
__global__ __launch_bounds__(128, 7) void passC_kernel(const float* __restrict__ x,
                                                       const float* __restrict__ D,
                                                       float* __restrict__ out) {
    int gw = (blockIdx.x * 128 + threadIdx.x) >> 5;
    int h  = threadIdx.x & 31;
    int b  = gw >> 8;
    int c  = gw & (NCHUNK - 1);
    int hb = h * NN2;

    ull a1[4], a2[4], b0[4], b1[4];
    #pragma unroll
    for (int v = 0; v < 4; v++) {
        a1[v] = pack2(g_a1[hb + 2 * v], g_a1[hb + 2 * v + 1]);
        a2[v] = pack2(g_a2[hb + 2 * v], g_a2[hb + 2 * v + 1]);
        b0[v] = pack2(g_b0[hb + 2 * v], g_b0[hb + 2 * v + 1]);
        b1[v] = pack2(g_b1[hb + 2 * v], g_b1[hb + 2 * v + 1]);
    }
    float Dh  = D[h];
    float gam = g_gamma[b * HH + h];
    float bet = g_beta[b * HH + h];

    // incoming complex state -> biquad states (v1 = v[t0-1], v2 = v[t0-2])
    ull v1[4], v2[4];
    {
        const ull* si = g_Sin + (size_t)(b * NCHUNK + c) * 8 * HH + h;
        #pragma unroll
        for (int v = 0; v < 4; v++) {
            ull k1 = pack2(g_k1[hb + 2 * v], g_k1[hb + 2 * v + 1]);
            ull k2 = pack2(g_k2[hb + 2 * v], g_k2[hb + 2 * v + 1]);
            ull sre = si[v * HH];
            ull sim = si[(4 + v) * HH];
            v1[v] = fma2(k1, sim, sre);
            v2[v] = mul2(k2, sim);
        }
    }

    const float* xp = x   + ((b * LL) + c * CLEN) * HH + h;
    float*       op = out + ((b * LL) + c * CLEN) * HH + h;

    #pragma unroll 2
    for (int j = 0; j < CLEN / 2; j++) {
        float u0 = xp[(2 * j) * HH];
        float u1 = xp[(2 * j + 1) * HH];
        ull u02 = pack2(u0, u0);
        ull u12 = pack2(u1, u1);

        // ---- step even: new v goes into v2 slot; output uses (v2_new, v1_old)
        #pragma unroll
        for (int v = 0; v < 4; v++) {
            ull t = fma2(a2[v], v2[v], u02);
            v2[v] = fma2(a1[v], v1[v], t);
        }
        {
            ull accA = pack2(Dh * u0, 0.0f);
            accA = fma2(b1[0], v1[0], accA);
            accA = fma2(b0[0], v2[0], accA);
            accA = fma2(b1[1], v1[1], accA);
            accA = fma2(b0[1], v2[1], accA);
            ull accB = mul2(b1[2], v1[2]);
            accB = fma2(b0[2], v2[2], accB);
            accB = fma2(b1[3], v1[3], accB);
            accB = fma2(b0[3], v2[3], accB);
            ull acc = add2(accA, accB);
            float lo, hi; unpack2(acc, lo, hi);
            op[(2 * j) * HH] = film_gelu(lo + hi, gam, bet);
        }

        // ---- step odd: new v goes into v1 slot; output uses (v1_new, v2)
        #pragma unroll
        for (int v = 0; v < 4; v++) {
            ull t = fma2(a2[v], v1[v], u12);
            v1[v] = fma2(a1[v], v2[v], t);
        }
        {
            ull accA = pack2(Dh * u1, 0.0f);
            accA = fma2(b1[0], v2[0], accA);
            accA = fma2(b0[0], v1[0], accA);
            accA = fma2(b1[1], v2[1], accA);
            accA = fma2(b0[1], v1[1], accA);
            ull accB = mul2(b1[2], v2[2]);
            accB = fma2(b0[2], v1[2], accB);
            accB = fma2(b1[3], v2[3], accB);
            accB = fma2(b0[3], v1[3], accB);
            ull acc = add2(accA, accB);
            float lo, hi; unpack2(acc, lo, hi);
            op[(2 * j + 1) * HH] = film_gelu(lo + hi, gam, bet);
        }
    }
}

extern "C" void kernel_launch(void* const* d_in, const int* in_sizes, int n_in,
                              void* d_out, int out_size) {
    const float* x          = (const float*)d_in[0];
    const float* cond       = (const float*)d_in[1];
    const float* log_dt     = (const float*)d_in[2];
    const float* C_re       = (const float*)d_in[3];
    const float* C_im       = (const float*)d_in[4];
    const float* log_A_real = (const float*)d_in[5];
    const float* A_imag     = (const float*)d_in[6];
    const float* D          = (const float*)d_in[7];
    const float* film_W     = (const float*)d_in[8];
    const float* film_b     = (const float*)d_in[9];
    float* out = (float*)d_out;

    precompute_kernel<<<1, 1024>>>(log_dt, C_re, C_im, log_A_real, A_imag, cond, film_W, film_b);
    passA_kernel<<<(BB * NCHUNK) / 4, 128>>>(x);
    passB_kernel<<<(BB * HH) / 4, 128>>>();
    passC_kernel<<<(BB * NCHUNK) / 4, 128>>>(x, D, out);
}